// round 8
// baseline (speedup 1.0000x reference)
#include <cuda_runtime.h>
#include <math.h>

// Problem constants
#define Bc   512
#define NAc  128
#define NLc  512
#define Dc   128
#define KAc  16
#define KLc  16
#define NNODES 32   // KA + KL

typedef unsigned long long u64;

// Scratch: computed node rows + selection.
__device__ float g_nodes[(size_t)Bc * NNODES * Dc];   // 8 MB
__device__ int   g_sel[Bc * NNODES];

// ---------------------------------------------------------------------------
// MLP dynamic shared layout (84224 bytes)
//   Xs / Hs: u64 [128][33]  — duplicated-pair activations, [k][row], pad 33
//   Wst:     float [2][16][128] — double-buffered weight stage
// ---------------------------------------------------------------------------
#define SM_XS   0            // 128*33*8 = 33792
#define SM_HS   33792        // 33792
#define SM_WST  67584        // 16384
#define SM_SSEL 83968        // int[32]
#define SM_TOTAL 84224

// ---------------------------------------------------------------------------
// helpers
// ---------------------------------------------------------------------------
__device__ __forceinline__ u64 pk2(float lo, float hi) {
    u64 r;
    asm("mov.b64 %0, {%1, %2};" : "=l"(r) : "f"(lo), "f"(hi));
    return r;
}
__device__ __forceinline__ void fma2(u64& d, u64 a, u64 b) {
    asm("fma.rn.f32x2 %0, %1, %2, %0;" : "+l"(d) : "l"(a), "l"(b));
}
__device__ __forceinline__ void unpk2(u64 v, float& lo, float& hi) {
    asm("mov.b64 {%0, %1}, %2;" : "=f"(lo), "=f"(hi) : "l"(v));
}
__device__ __forceinline__ void cpa16(void* smem_dst, const void* gsrc) {
    unsigned sa = (unsigned)__cvta_generic_to_shared(smem_dst);
    asm volatile("cp.async.cg.shared.global [%0], [%1], 16;"
                 :: "r"(sa), "l"(gsrc));
}
#define CP_COMMIT() asm volatile("cp.async.commit_group;")
#define CP_WAIT0()  asm volatile("cp.async.wait_group 0;")

// butterfly sum across 8-lane group (lane bits 0..2 = col-group)
__device__ __forceinline__ float wsum8(float v) {
    #pragma unroll
    for (int o = 4; o > 0; o >>= 1) v += __shfl_xor_sync(0xffffffffu, v, o);
    return v;
}
__device__ __forceinline__ float gelu_exact(float x) {
    return 0.5f * x * (1.0f + erff(x * 0.70710678118654752440f));
}

// ---------------------------------------------------------------------------
// Kernel 1: selection (proven R2..R7). One block per batch.
// ---------------------------------------------------------------------------
__global__ void __launch_bounds__(128)
select_kernel(const float* __restrict__ lane_centers,
              const float* __restrict__ x_centers,
              const float* __restrict__ spike_rate,
              const void*  __restrict__ actor_valid_raw,
              const void*  __restrict__ lane_valid_raw)
{
    __shared__ float sv[NAc];
    __shared__ float ld[NLc];
    __shared__ int   sel[NNODES];
    __shared__ float ax[KAc], ay[KAc];

    const int tid = threadIdx.x;
    const int b   = blockIdx.x;

    // ---- Phase 0: detect boolean encoding (uint8 / int32 / float32) ----
    int enc;
    {
        const unsigned char* p =
            (const unsigned char*)lane_valid_raw + (size_t)b * 512;
        unsigned char b1 = p[tid * 4 + 1];
        unsigned char b2 = p[tid * 4 + 2];
        unsigned char b3 = p[tid * 4 + 3];
        int any1   = __syncthreads_or((int)b1);
        int anyOff = __syncthreads_or((int)(b1 | b2 | b3));
        enc = anyOff ? (any1 ? 0 : 2) : 1;
    }

    // ---- Phase A: actor top-16 (stable, jax top_k tie rule) ----
    {
        bool av;
        if (enc == 0)      av = ((const unsigned char*)actor_valid_raw)[(size_t)b * NAc + tid] != 0;
        else if (enc == 1) av = ((const int*)actor_valid_raw)[(size_t)b * NAc + tid] != 0;
        else               av = ((const float*)actor_valid_raw)[(size_t)b * NAc + tid] != 0.0f;
        float v = spike_rate[b * NAc + tid];
        sv[tid] = av ? v : -INFINITY;
    }
    __syncthreads();
    {
        float mv = sv[tid];
        int cnt = 0;
        #pragma unroll 8
        for (int j = 0; j < NAc; j++) {
            float o = sv[j];
            cnt += (o > mv) || (o == mv && j < tid);
        }
        if (cnt < KAc) sel[cnt] = tid;
    }
    __syncthreads();
    if (tid < KAc) {
        int a = sel[tid];
        ax[tid] = x_centers[((size_t)b * NAc + a) * 2 + 0];
        ay[tid] = x_centers[((size_t)b * NAc + a) * 2 + 1];
    }
    __syncthreads();

    // ---- Phase B: lane distances + top-16 smallest ----
    #pragma unroll
    for (int q = 0; q < 4; q++) {
        int l = tid + 128 * q;
        bool lv;
        if (enc == 0)      lv = ((const unsigned char*)lane_valid_raw)[(size_t)b * NLc + l] != 0;
        else if (enc == 1) lv = ((const int*)lane_valid_raw)[(size_t)b * NLc + l] != 0;
        else               lv = ((const float*)lane_valid_raw)[(size_t)b * NLc + l] != 0.0f;
        float d = INFINITY;
        if (lv) {
            float lx = lane_centers[((size_t)b * NLc + l) * 2 + 0];
            float ly = lane_centers[((size_t)b * NLc + l) * 2 + 1];
            float m2 = INFINITY;
            #pragma unroll
            for (int a = 0; a < KAc; a++) {
                float dx = __fadd_rn(ax[a], -lx);
                float dy = __fadd_rn(ay[a], -ly);
                float s = __fadd_rn(__fmul_rn(dx, dx), __fmul_rn(dy, dy));
                m2 = fminf(m2, s);
            }
            d = sqrtf(m2);   // sqrt monotone: min(sqrt(s)) == sqrt(min(s))
        }
        ld[l] = d;
    }
    __syncthreads();
    {
        float dl[4];
        int   cnt[4];
        #pragma unroll
        for (int q = 0; q < 4; q++) { dl[q] = ld[tid + 128 * q]; cnt[q] = 0; }
        #pragma unroll 4
        for (int j = 0; j < NLc; j++) {
            float o = ld[j];
            #pragma unroll
            for (int q = 0; q < 4; q++) {
                int l = tid + 128 * q;
                cnt[q] += (o < dl[q]) || (o == dl[q] && j < l);
            }
        }
        #pragma unroll
        for (int q = 0; q < 4; q++)
            if (cnt[q] < KLc) sel[KAc + cnt[q]] = tid + 128 * q;
    }
    __syncthreads();

    if (tid < NNODES) g_sel[b * NNODES + tid] = sel[tid];
}

// ---------------------------------------------------------------------------
// 32x128 @ 128x128 GEMM, 256 threads, dup-A layout, double-buffered W.
// A: u64[128][33], A[k][r] = (x[r][k], x[r][k]).  Thread (r = tid>>3, g = tid&7)
// owns row r, cols 16g..16g+15.  acc[j] = col pair (16g+2j, 16g+2j+1).
// B operand comes straight from W via LDS.128 -> 2 u64 (no packing).
// ---------------------------------------------------------------------------
__device__ __forceinline__ void gemm_dup(
    const u64 (*A)[33], const float* __restrict__ W,
    float (*Wst)[16][128], int tid, int r, int g, u64 (&acc)[8])
{
    #pragma unroll
    for (int j = 0; j < 8; j++) acc[j] = 0ull;

    {   // prologue: stage 0 (16x128 fp32 = 8KB), 2x16B per thread
        float* dst = &Wst[0][0][0];
        cpa16(dst + tid * 4,         W + tid * 4);
        cpa16(dst + (tid + 256) * 4, W + (tid + 256) * 4);
        CP_COMMIT();
    }

    #pragma unroll 1
    for (int s = 0; s < 8; s++) {
        CP_WAIT0();
        __syncthreads();
        if (s < 7) {
            float* dst = &Wst[(s + 1) & 1][0][0];
            const float* src = W + (s + 1) * 2048;
            cpa16(dst + tid * 4,         src + tid * 4);
            cpa16(dst + (tid + 256) * 4, src + (tid + 256) * 4);
            CP_COMMIT();
        }
        #pragma unroll
        for (int kk = 0; kk < 16; kk++) {
            const ulonglong2* row =
                (const ulonglong2*)&Wst[s & 1][kk][0];
            ulonglong2 p0 = row[4 * g + 0];   // cols 16g+0..3 (two pairs)
            ulonglong2 p1 = row[4 * g + 1];
            ulonglong2 p2 = row[4 * g + 2];
            ulonglong2 p3 = row[4 * g + 3];
            u64 a2 = A[s * 16 + kk][r];
            fma2(acc[0], a2, p0.x); fma2(acc[1], a2, p0.y);
            fma2(acc[2], a2, p1.x); fma2(acc[3], a2, p1.y);
            fma2(acc[4], a2, p2.x); fma2(acc[5], a2, p2.y);
            fma2(acc[6], a2, p3.x); fma2(acc[7], a2, p3.y);
        }
    }
}

// ---------------------------------------------------------------------------
// Kernel 2: MLP. One batch per block, 256 threads.
// ---------------------------------------------------------------------------
__global__ void __launch_bounds__(256, 2)
mlp_kernel(const float* __restrict__ actor_feat,
           const float* __restrict__ lane_feat,
           const float* __restrict__ W0a, const float* __restrict__ b0a,
           const float* __restrict__ W0b, const float* __restrict__ b0b,
           const float* __restrict__ W1a, const float* __restrict__ b1a,
           const float* __restrict__ W1b, const float* __restrict__ b1b,
           const float* __restrict__ gmm, const float* __restrict__ bta)
{
    extern __shared__ unsigned char smem_raw[];
    u64 (*Xs)[33]        = (u64 (*)[33])(smem_raw + SM_XS);
    u64 (*Hs)[33]        = (u64 (*)[33])(smem_raw + SM_HS);
    float (*Wst)[16][128] = (float (*)[16][128])(smem_raw + SM_WST);
    int* ssel            = (int*)(smem_raw + SM_SSEL);

    const int tid = threadIdx.x;
    const int b   = blockIdx.x;
    const int r   = tid >> 3;    // row 0..31
    const int g   = tid & 7;     // col group (16 cols)

    if (tid < NNODES) ssel[tid] = g_sel[b * NNODES + tid];
    __syncthreads();

    // ---- gather: thread = (half, feature col); writes duplicated pairs ----
    {
        int colG = tid & 127;
        int half = tid >> 7;
        #pragma unroll 4
        for (int rr = 0; rr < 16; rr++) {
            int rw  = half * 16 + rr;     // half 0 -> actor rows, 1 -> lanes
            int idx = ssel[rw];
            const float* src = half
                ? (lane_feat  + ((size_t)b * NLc + idx) * Dc)
                : (actor_feat + ((size_t)b * NAc + idx) * Dc);
            float v = src[colG];
            Xs[colG][rw] = pk2(v, v);
        }
    }
    // ordering with GEMM reads: behind gemm_dup's internal stage-0 barrier

    u64 acc[8];

    #pragma unroll 1
    for (int layer = 0; layer < 2; layer++) {
        const float* Wa  = layer ? W1a : W0a;
        const float* ba  = layer ? b1a : b0a;
        const float* Wb2 = layer ? W1b : W0b;
        const float* bb2 = layer ? b1b : b0b;

        // ---- GEMM1: H = gelu(X @ Wa + ba) -> Hs (dup pairs) ----
        gemm_dup(Xs, Wa, Wst, tid, r, g, acc);
        {
            float v[16];
            #pragma unroll
            for (int j = 0; j < 8; j++) unpk2(acc[j], v[2 * j], v[2 * j + 1]);
            #pragma unroll
            for (int i = 0; i < 4; i++) {
                float4 bq = *(const float4*)(ba + 16 * g + 4 * i);
                v[4 * i + 0] = gelu_exact(v[4 * i + 0] + bq.x);
                v[4 * i + 1] = gelu_exact(v[4 * i + 1] + bq.y);
                v[4 * i + 2] = gelu_exact(v[4 * i + 2] + bq.z);
                v[4 * i + 3] = gelu_exact(v[4 * i + 3] + bq.w);
            }
            #pragma unroll
            for (int j = 0; j < 16; j++)
                Hs[16 * g + j][r] = pk2(v[j], v[j]);
        }
        // Hs writes vs GEMM2 reads ordered by gemm_dup's internal barrier

        // ---- GEMM2: Y = H @ Wb + bb; Z = LN(X + Y) ----
        gemm_dup(Hs, Wb2, Wst, tid, r, g, acc);
        {
            float v[16];
            #pragma unroll
            for (int j = 0; j < 8; j++) unpk2(acc[j], v[2 * j], v[2 * j + 1]);
            #pragma unroll
            for (int i = 0; i < 4; i++) {
                float4 bq = *(const float4*)(bb2 + 16 * g + 4 * i);
                v[4 * i + 0] += bq.x; v[4 * i + 1] += bq.y;
                v[4 * i + 2] += bq.z; v[4 * i + 3] += bq.w;
            }
            // residual (own cols only; dup pair -> take lo)
            #pragma unroll
            for (int j = 0; j < 16; j++) {
                float lo, hi; unpk2(Xs[16 * g + j][r], lo, hi);
                v[j] += lo;
            }
            float s = 0.f;
            #pragma unroll
            for (int j = 0; j < 16; j++) s += v[j];
            float m = wsum8(s) * 0.0078125f;
            float q = 0.f;
            #pragma unroll
            for (int j = 0; j < 16; j++) { float d = v[j] - m; q += d * d; }
            float inv = rsqrtf(wsum8(q) * 0.0078125f + 1e-5f);

            if (layer == 0) {
                #pragma unroll
                for (int i = 0; i < 4; i++) {
                    float4 gq = *(const float4*)(gmm + 16 * g + 4 * i);
                    float4 pq = *(const float4*)(bta + 16 * g + 4 * i);
                    float z0 = (v[4 * i + 0] - m) * inv * gq.x + pq.x;
                    float z1 = (v[4 * i + 1] - m) * inv * gq.y + pq.y;
                    float z2 = (v[4 * i + 2] - m) * inv * gq.z + pq.z;
                    float z3 = (v[4 * i + 3] - m) * inv * gq.w + pq.w;
                    Xs[16 * g + 4 * i + 0][r] = pk2(z0, z0);
                    Xs[16 * g + 4 * i + 1][r] = pk2(z1, z1);
                    Xs[16 * g + 4 * i + 2][r] = pk2(z2, z2);
                    Xs[16 * g + 4 * i + 3][r] = pk2(z3, z3);
                }
                // next GEMM's reads are behind its internal stage-0 barrier
            } else {
                float* dst = g_nodes + ((size_t)b * NNODES + r) * Dc + 16 * g;
                #pragma unroll
                for (int i = 0; i < 4; i++) {
                    float4 gq = *(const float4*)(gmm + 16 * g + 4 * i);
                    float4 pq = *(const float4*)(bta + 16 * g + 4 * i);
                    float4 o;
                    o.x = (v[4 * i + 0] - m) * inv * gq.x + pq.x;
                    o.y = (v[4 * i + 1] - m) * inv * gq.y + pq.y;
                    o.z = (v[4 * i + 2] - m) * inv * gq.z + pq.z;
                    o.w = (v[4 * i + 3] - m) * inv * gq.w + pq.w;
                    *(float4*)(dst + 4 * i) = o;
                }
            }
        }
    }
}

// ---------------------------------------------------------------------------
// Copy kernel: both pools -> out (forked stream; overlaps select+mlp)
// ---------------------------------------------------------------------------
__global__ void __launch_bounds__(256)
copy_kernel(const float4* __restrict__ a, const float4* __restrict__ l,
            float4* __restrict__ out)
{
    const size_t na = (size_t)Bc * NAc * Dc / 4;
    const size_t nt = na + (size_t)Bc * NLc * Dc / 4;
    size_t step = (size_t)gridDim.x * 256;
    for (size_t i = (size_t)blockIdx.x * 256 + threadIdx.x; i < nt; i += step)
        out[i] = (i < na) ? a[i] : l[i - na];
}

// ---------------------------------------------------------------------------
// Scatter kernel: warp per row, float4 lanes (proven R5).
// ---------------------------------------------------------------------------
__global__ void __launch_bounds__(256)
scatter_kernel(float* __restrict__ out)
{
    __shared__ int ssel[NNODES];
    const int tid = threadIdx.x;
    const int b   = blockIdx.x;
    if (tid < NNODES) ssel[tid] = g_sel[b * NNODES + tid];
    __syncthreads();
    const int w = tid >> 5, lane = tid & 31;
    const size_t lane_base = (size_t)Bc * NAc * Dc;
    #pragma unroll
    for (int it = 0; it < 4; it++) {
        int rr = it * 8 + w;
        int idx = ssel[rr];
        size_t base = (rr < KAc)
            ? ((size_t)b * NAc + idx) * Dc
            : lane_base + ((size_t)b * NLc + idx) * Dc;
        ((float4*)(out + base))[lane] =
            ((const float4*)(g_nodes + ((size_t)b * NNODES + rr) * Dc))[lane];
    }
}

// ---------------------------------------------------------------------------
// kernel_launch: copy forked at the very start (independent of selection);
// main stream runs select -> mlp; join; scatter overwrites selected rows.
// ---------------------------------------------------------------------------
extern "C" void kernel_launch(void* const* d_in, const int* in_sizes, int n_in,
                              void* d_out, int out_size)
{
    const float* actor_feat   = (const float*)d_in[0];
    const float* lane_feat    = (const float*)d_in[1];
    const float* lane_centers = (const float*)d_in[2];
    const float* x_centers    = (const float*)d_in[3];
    const float* spike_rate   = (const float*)d_in[4];
    const void*  actor_valid  = d_in[5];
    const void*  lane_valid   = d_in[6];
    const float* W0a = (const float*)d_in[7];
    const float* b0a = (const float*)d_in[8];
    const float* W0b = (const float*)d_in[9];
    const float* b0b = (const float*)d_in[10];
    const float* W1a = (const float*)d_in[11];
    const float* b1a = (const float*)d_in[12];
    const float* W1b = (const float*)d_in[13];
    const float* b1b = (const float*)d_in[14];
    const float* gmm = (const float*)d_in[15];
    const float* bta = (const float*)d_in[16];
    float* out = (float*)d_out;

    cudaFuncSetAttribute(mlp_kernel,
                         cudaFuncAttributeMaxDynamicSharedMemorySize, SM_TOTAL);

    cudaStream_t s2;
    cudaEvent_t eA, eB;
    cudaStreamCreateWithFlags(&s2, cudaStreamNonBlocking);
    cudaEventCreateWithFlags(&eA, cudaEventDisableTiming);
    cudaEventCreateWithFlags(&eB, cudaEventDisableTiming);

    // Fork copy immediately (depends only on inputs).
    cudaEventRecord(eA, 0);
    cudaStreamWaitEvent(s2, eA, 0);
    copy_kernel<<<1184, 256, 0, s2>>>((const float4*)actor_feat,
                                      (const float4*)lane_feat, (float4*)out);
    cudaEventRecord(eB, s2);

    // Main stream: selection then MLP (concurrent with the copy).
    select_kernel<<<Bc, 128>>>(lane_centers, x_centers, spike_rate,
                               actor_valid, lane_valid);
    mlp_kernel<<<Bc, 256, SM_TOTAL>>>(actor_feat, lane_feat,
                                      W0a, b0a, W0b, b0b,
                                      W1a, b1a, W1b, b1b,
                                      gmm, bta);

    // Join, then overwrite the 32 selected rows per batch.
    cudaStreamWaitEvent(0, eB, 0);
    scatter_kernel<<<Bc, 256>>>(out);
}

// round 9
// speedup vs baseline: 3.9092x; 3.9092x over previous
#include <cuda_runtime.h>
#include <math.h>

// Problem constants
#define Bc   512
#define NAc  128
#define NLc  512
#define Dc   128
#define KAc  16
#define KLc  16
#define NNODES 32   // KA + KL

typedef unsigned long long u64;

// Scratch: nodes, selection, redirect maps.
__device__ float g_nodes[(size_t)Bc * NNODES * Dc];   // 8 MB
__device__ int   g_sel[Bc * NNODES];
__device__ int   g_redir_a[Bc * NAc];    // -1 or node index 0..15
__device__ int   g_redir_l[Bc * NLc];    // -1 or node index 16..31

// ---------------------------------------------------------------------------
// MLP dynamic shared layout (53376 bytes -> 4 blocks/SM, single wave)
//   Xs/Hs: float [128][36], transposed [k][row] (row stride 36 floats = 144B,
//          16B-aligned rows; 4rg offsets 16B-aligned for LDS.128)
//   Wst:   float [2][2048] double-buffered weight stage (8KB each)
// ---------------------------------------------------------------------------
#define SM_XS    0        // 18432
#define SM_HS    18432    // 18432
#define SM_WST   36864    // 16384
#define SM_SSEL  53248    // 128
#define SM_TOTAL 53376

// ---------------------------------------------------------------------------
// helpers
// ---------------------------------------------------------------------------
__device__ __forceinline__ u64 pk2(float lo, float hi) {
    u64 r;
    asm("mov.b64 %0, {%1, %2};" : "=l"(r) : "f"(lo), "f"(hi));
    return r;
}
__device__ __forceinline__ void fma2(u64& d, u64 a, u64 b) {
    asm("fma.rn.f32x2 %0, %1, %2, %0;" : "+l"(d) : "l"(a), "l"(b));
}
__device__ __forceinline__ void unpk2(u64 v, float& lo, float& hi) {
    asm("mov.b64 {%0, %1}, %2;" : "=f"(lo), "=f"(hi) : "l"(v));
}
__device__ __forceinline__ void cpa16(void* smem_dst, const void* gsrc) {
    unsigned sa = (unsigned)__cvta_generic_to_shared(smem_dst);
    asm volatile("cp.async.cg.shared.global [%0], [%1], 16;"
                 :: "r"(sa), "l"(gsrc));
}
#define CP_COMMIT() asm volatile("cp.async.commit_group;")
#define CP_WAIT0()  asm volatile("cp.async.wait_group 0;")

__device__ __forceinline__ float wsum32(float v) {
    #pragma unroll
    for (int o = 16; o > 0; o >>= 1) v += __shfl_xor_sync(0xffffffffu, v, o);
    return v;
}
__device__ __forceinline__ float gelu_exact(float x) {
    return 0.5f * x * (1.0f + erff(x * 0.70710678118654752440f));
}

// ---------------------------------------------------------------------------
// Kernel 1: selection (proven R2..R8) + redirect maps (proven R7).
// ---------------------------------------------------------------------------
__global__ void __launch_bounds__(128)
select_kernel(const float* __restrict__ lane_centers,
              const float* __restrict__ x_centers,
              const float* __restrict__ spike_rate,
              const void*  __restrict__ actor_valid_raw,
              const void*  __restrict__ lane_valid_raw)
{
    __shared__ float sv[NAc];
    __shared__ float ld[NLc];
    __shared__ int   sel[NNODES];
    __shared__ float ax[KAc], ay[KAc];

    const int tid = threadIdx.x;
    const int b   = blockIdx.x;

    // init redirect maps
    g_redir_a[b * NAc + tid] = -1;
    #pragma unroll
    for (int q = 0; q < 4; q++)
        g_redir_l[b * NLc + tid + 128 * q] = -1;

    // ---- Phase 0: detect boolean encoding (uint8 / int32 / float32) ----
    int enc;
    {
        const unsigned char* p =
            (const unsigned char*)lane_valid_raw + (size_t)b * 512;
        unsigned char b1 = p[tid * 4 + 1];
        unsigned char b2 = p[tid * 4 + 2];
        unsigned char b3 = p[tid * 4 + 3];
        int any1   = __syncthreads_or((int)b1);
        int anyOff = __syncthreads_or((int)(b1 | b2 | b3));
        enc = anyOff ? (any1 ? 0 : 2) : 1;
    }

    // ---- Phase A: actor top-16 (stable, jax top_k tie rule) ----
    {
        bool av;
        if (enc == 0)      av = ((const unsigned char*)actor_valid_raw)[(size_t)b * NAc + tid] != 0;
        else if (enc == 1) av = ((const int*)actor_valid_raw)[(size_t)b * NAc + tid] != 0;
        else               av = ((const float*)actor_valid_raw)[(size_t)b * NAc + tid] != 0.0f;
        float v = spike_rate[b * NAc + tid];
        sv[tid] = av ? v : -INFINITY;
    }
    __syncthreads();
    {
        float mv = sv[tid];
        int cnt = 0;
        #pragma unroll 8
        for (int j = 0; j < NAc; j++) {
            float o = sv[j];
            cnt += (o > mv) || (o == mv && j < tid);
        }
        if (cnt < KAc) sel[cnt] = tid;
    }
    __syncthreads();
    if (tid < KAc) {
        int a = sel[tid];
        ax[tid] = x_centers[((size_t)b * NAc + a) * 2 + 0];
        ay[tid] = x_centers[((size_t)b * NAc + a) * 2 + 1];
    }
    __syncthreads();

    // ---- Phase B: lane distances + top-16 smallest ----
    #pragma unroll
    for (int q = 0; q < 4; q++) {
        int l = tid + 128 * q;
        bool lv;
        if (enc == 0)      lv = ((const unsigned char*)lane_valid_raw)[(size_t)b * NLc + l] != 0;
        else if (enc == 1) lv = ((const int*)lane_valid_raw)[(size_t)b * NLc + l] != 0;
        else               lv = ((const float*)lane_valid_raw)[(size_t)b * NLc + l] != 0.0f;
        float d = INFINITY;
        if (lv) {
            float lx = lane_centers[((size_t)b * NLc + l) * 2 + 0];
            float ly = lane_centers[((size_t)b * NLc + l) * 2 + 1];
            float m2 = INFINITY;
            #pragma unroll
            for (int a = 0; a < KAc; a++) {
                float dx = __fadd_rn(ax[a], -lx);
                float dy = __fadd_rn(ay[a], -ly);
                float s = __fadd_rn(__fmul_rn(dx, dx), __fmul_rn(dy, dy));
                m2 = fminf(m2, s);
            }
            d = sqrtf(m2);   // sqrt monotone: min(sqrt(s)) == sqrt(min(s))
        }
        ld[l] = d;
    }
    __syncthreads();
    {
        float dl[4];
        int   cnt[4];
        #pragma unroll
        for (int q = 0; q < 4; q++) { dl[q] = ld[tid + 128 * q]; cnt[q] = 0; }
        #pragma unroll 4
        for (int j = 0; j < NLc; j++) {
            float o = ld[j];
            #pragma unroll
            for (int q = 0; q < 4; q++) {
                int l = tid + 128 * q;
                cnt[q] += (o < dl[q]) || (o == dl[q] && j < l);
            }
        }
        #pragma unroll
        for (int q = 0; q < 4; q++)
            if (cnt[q] < KLc) sel[KAc + cnt[q]] = tid + 128 * q;
    }
    __syncthreads();

    if (tid < KAc) {
        g_redir_a[b * NAc + sel[tid]] = tid;
        g_sel[b * NNODES + tid] = sel[tid];
    } else if (tid < NNODES) {
        g_redir_l[b * NLc + sel[tid]] = tid;
        g_sel[b * NNODES + tid] = sel[tid];
    }
}

// ---------------------------------------------------------------------------
// 32x128 @ 128x128 GEMM, 256 threads, cp.async double-buffered W (R5 scheme).
// A: float [128][36] transposed [k][row]. Warp rg (tid>>5): rows 4rg..4rg+3
// (one broadcast LDS.128 -> two row-pair u64s, no packing). Lane cg (tid&31):
// cols 4cg..4cg+3 (one conflict-free LDS.128; 4 pk2 dups).
// acc[rp][c]: rp0 = rows (4rg,4rg+1), rp1 = rows (4rg+2,4rg+3); col 4cg+c.
// ---------------------------------------------------------------------------
__device__ __forceinline__ void gemm_rc(
    const float* A, const float* __restrict__ Wg,
    float* Wst, int tid, int rg, int cg, u64 (&acc)[2][4])
{
    #pragma unroll
    for (int rp = 0; rp < 2; rp++)
        #pragma unroll
        for (int c = 0; c < 4; c++) acc[rp][c] = 0ull;

    // prologue: stage 0 (16x128 fp32 = 8KB), 2x16B per thread
    cpa16(Wst + tid * 4,        Wg + tid * 4);
    cpa16(Wst + 1024 + tid * 4, Wg + 1024 + tid * 4);
    CP_COMMIT();

    #pragma unroll 1
    for (int s = 0; s < 8; s++) {
        CP_WAIT0();          // this thread's stage-s copies landed
        __syncthreads();     // all threads: data visible; prior stage reads done
        if (s < 7) {
            float* dst = Wst + ((s + 1) & 1) * 2048;
            const float* src = Wg + (s + 1) * 2048;
            cpa16(dst + tid * 4,        src + tid * 4);
            cpa16(dst + 1024 + tid * 4, src + 1024 + tid * 4);
            CP_COMMIT();
        }
        const float* Ws = Wst + (s & 1) * 2048;
        const float* Ab = A + s * 16 * 36 + 4 * rg;
        #pragma unroll
        for (int kk = 0; kk < 16; kk++) {
            float4 w = *(const float4*)(Ws + kk * 128 + 4 * cg);
            u64 bx = pk2(w.x, w.x);
            u64 by = pk2(w.y, w.y);
            u64 bz = pk2(w.z, w.z);
            u64 bw = pk2(w.w, w.w);
            ulonglong2 a = *(const ulonglong2*)(Ab + kk * 36);
            fma2(acc[0][0], a.x, bx); fma2(acc[0][1], a.x, by);
            fma2(acc[0][2], a.x, bz); fma2(acc[0][3], a.x, bw);
            fma2(acc[1][0], a.y, bx); fma2(acc[1][1], a.y, by);
            fma2(acc[1][2], a.y, bz); fma2(acc[1][3], a.y, bw);
        }
    }
}

// ---------------------------------------------------------------------------
// Kernel 2: MLP. One batch per block, 256 threads, 4 blocks/SM (single wave).
// ---------------------------------------------------------------------------
__global__ void __launch_bounds__(256, 4)
mlp_kernel(const float* __restrict__ actor_feat,
           const float* __restrict__ lane_feat,
           const float* __restrict__ W0a, const float* __restrict__ b0a,
           const float* __restrict__ W0b, const float* __restrict__ b0b,
           const float* __restrict__ W1a, const float* __restrict__ b1a,
           const float* __restrict__ W1b, const float* __restrict__ b1b,
           const float* __restrict__ gmm, const float* __restrict__ bta)
{
    extern __shared__ unsigned char smem_raw[];
    float* Xs  = (float*)(smem_raw + SM_XS);    // [k][row], stride 36
    float* Hs  = (float*)(smem_raw + SM_HS);
    float* Wst = (float*)(smem_raw + SM_WST);
    int*  ssel = (int*)(smem_raw + SM_SSEL);

    const int tid = threadIdx.x;
    const int b   = blockIdx.x;
    const int rg  = tid >> 5;    // warp -> rows 4rg..4rg+3
    const int cg  = tid & 31;    // lane -> cols 4cg..4cg+3

    if (tid < NNODES) ssel[tid] = g_sel[b * NNODES + tid];
    __syncthreads();

    // ---- gather: thread = (half, feature col) ----
    {
        int colG = tid & 127;
        int half = tid >> 7;
        #pragma unroll 4
        for (int rr = 0; rr < 16; rr++) {
            int rw  = half * 16 + rr;
            int idx = ssel[rw];
            const float* src = half
                ? (lane_feat  + ((size_t)b * NLc + idx) * Dc)
                : (actor_feat + ((size_t)b * NAc + idx) * Dc);
            Xs[colG * 36 + rw] = src[colG];
        }
    }
    // visibility to GEMM1 reads: behind gemm_rc's stage-0 sync

    u64 acc[2][4];

    #pragma unroll 1
    for (int layer = 0; layer < 2; layer++) {
        const float* Wa  = layer ? W1a : W0a;
        const float* ba  = layer ? b1a : b0a;
        const float* Wb2 = layer ? W1b : W0b;
        const float* bb2 = layer ? b1b : b0b;

        // ---- GEMM1: H = gelu(X @ Wa + ba) -> Hs ----
        gemm_rc(Xs, Wa, Wst, tid, rg, cg, acc);
        {
            float4 bq = *(const float4*)(ba + 4 * cg);
            float bar[4] = {bq.x, bq.y, bq.z, bq.w};
            #pragma unroll
            for (int rp = 0; rp < 2; rp++) {
                int r0 = 4 * rg + 2 * rp;
                #pragma unroll
                for (int c = 0; c < 4; c++) {
                    float lo, hi; unpk2(acc[rp][c], lo, hi);
                    lo = gelu_exact(lo + bar[c]);
                    hi = gelu_exact(hi + bar[c]);
                    *(float2*)(Hs + (4 * cg + c) * 36 + r0) = make_float2(lo, hi);
                }
            }
        }
        // Hs writes vs GEMM2 reads: behind gemm_rc's stage-0 sync

        // ---- GEMM2: Y = H @ Wb + bb; Z = LN(X + Y) ----
        gemm_rc(Hs, Wb2, Wst, tid, rg, cg, acc);
        {
            float4 bq = *(const float4*)(bb2 + 4 * cg);
            float bbr[4] = {bq.x, bq.y, bq.z, bq.w};
            float4 gq = *(const float4*)(gmm + 4 * cg);
            float4 pq = *(const float4*)(bta + 4 * cg);
            float gar[4] = {gq.x, gq.y, gq.z, gq.w};
            float per[4] = {pq.x, pq.y, pq.z, pq.w};

            #pragma unroll
            for (int rp = 0; rp < 2; rp++) {
                int r0 = 4 * rg + 2 * rp;
                float l0[4], l1[4];
                #pragma unroll
                for (int c = 0; c < 4; c++) {
                    float lo, hi; unpk2(acc[rp][c], lo, hi);
                    float2 xv = *(const float2*)(Xs + (4 * cg + c) * 36 + r0);
                    l0[c] = lo + bbr[c] + xv.x;
                    l1[c] = hi + bbr[c] + xv.y;
                }
                float m0 = wsum32(l0[0] + l0[1] + l0[2] + l0[3]) * 0.0078125f;
                float m1 = wsum32(l1[0] + l1[1] + l1[2] + l1[3]) * 0.0078125f;
                float q0 = 0.f, q1 = 0.f;
                #pragma unroll
                for (int c = 0; c < 4; c++) {
                    float d0 = l0[c] - m0; q0 += d0 * d0;
                    float d1 = l1[c] - m1; q1 += d1 * d1;
                }
                float i0 = rsqrtf(wsum32(q0) * 0.0078125f + 1e-5f);
                float i1 = rsqrtf(wsum32(q1) * 0.0078125f + 1e-5f);

                if (layer == 0) {
                    // writeback own cells (residual reads above were own-cell)
                    #pragma unroll
                    for (int c = 0; c < 4; c++) {
                        float z0 = (l0[c] - m0) * i0 * gar[c] + per[c];
                        float z1 = (l1[c] - m1) * i1 * gar[c] + per[c];
                        *(float2*)(Xs + (4 * cg + c) * 36 + r0) = make_float2(z0, z1);
                    }
                } else {
                    float4 o0, o1;
                    o0.x = (l0[0] - m0) * i0 * gar[0] + per[0];
                    o0.y = (l0[1] - m0) * i0 * gar[1] + per[1];
                    o0.z = (l0[2] - m0) * i0 * gar[2] + per[2];
                    o0.w = (l0[3] - m0) * i0 * gar[3] + per[3];
                    o1.x = (l1[0] - m1) * i1 * gar[0] + per[0];
                    o1.y = (l1[1] - m1) * i1 * gar[1] + per[1];
                    o1.z = (l1[2] - m1) * i1 * gar[2] + per[2];
                    o1.w = (l1[3] - m1) * i1 * gar[3] + per[3];
                    float* d0 = g_nodes + ((size_t)b * NNODES + r0) * Dc + 4 * cg;
                    *(float4*)d0        = o0;
                    *(float4*)(d0 + Dc) = o1;
                }
            }
        }
    }
}

// ---------------------------------------------------------------------------
// Kernel 3: assemble (fused copy + scatter; proven R7 ~50us). Warp per row.
// ---------------------------------------------------------------------------
__global__ void __launch_bounds__(256)
assemble_kernel(const float4* __restrict__ actor,
                const float4* __restrict__ lane,
                float4* __restrict__ out)
{
    const int gw   = (blockIdx.x * 256 + threadIdx.x) >> 5;
    const int ln   = threadIdx.x & 31;
    const int nw   = (gridDim.x * 256) >> 5;
    const int TOTA = Bc * NAc;
    const int TOT  = TOTA + Bc * NLc;
    const float4* nodes = (const float4*)g_nodes;

    for (int R = gw; R < TOT; R += nw) {
        const float4* src;
        if (R < TOTA) {
            int n = g_redir_a[R];
            src = (n < 0) ? (actor + (size_t)R * 32)
                          : (nodes + ((size_t)(R >> 7) * NNODES + n) * 32);
        } else {
            int rl = R - TOTA;
            int n = g_redir_l[rl];
            src = (n < 0) ? (lane + (size_t)rl * 32)
                          : (nodes + ((size_t)(rl >> 9) * NNODES + n) * 32);
        }
        out[(size_t)R * 32 + ln] = src[ln];
    }
}

__global__ void nop_kernel() {}

// ---------------------------------------------------------------------------
// kernel_launch: select -> nop,nop -> mlp -> assemble.
// (6th captured launch = 4th user launch = mlp; 2 harness memsets precede.)
// ---------------------------------------------------------------------------
extern "C" void kernel_launch(void* const* d_in, const int* in_sizes, int n_in,
                              void* d_out, int out_size)
{
    const float* actor_feat   = (const float*)d_in[0];
    const float* lane_feat    = (const float*)d_in[1];
    const float* lane_centers = (const float*)d_in[2];
    const float* x_centers    = (const float*)d_in[3];
    const float* spike_rate   = (const float*)d_in[4];
    const void*  actor_valid  = d_in[5];
    const void*  lane_valid   = d_in[6];
    const float* W0a = (const float*)d_in[7];
    const float* b0a = (const float*)d_in[8];
    const float* W0b = (const float*)d_in[9];
    const float* b0b = (const float*)d_in[10];
    const float* W1a = (const float*)d_in[11];
    const float* b1a = (const float*)d_in[12];
    const float* W1b = (const float*)d_in[13];
    const float* b1b = (const float*)d_in[14];
    const float* gmm = (const float*)d_in[15];
    const float* bta = (const float*)d_in[16];
    float* out = (float*)d_out;

    cudaFuncSetAttribute(mlp_kernel,
                         cudaFuncAttributeMaxDynamicSharedMemorySize, SM_TOTAL);

    select_kernel<<<Bc, 128>>>(lane_centers, x_centers, spike_rate,
                               actor_valid, lane_valid);
    nop_kernel<<<1, 32>>>();
    nop_kernel<<<1, 32>>>();
    mlp_kernel<<<Bc, 256, SM_TOTAL>>>(actor_feat, lane_feat,
                                      W0a, b0a, W0b, b0b,
                                      W1a, b1a, W1b, b1b,
                                      gmm, bta);
    assemble_kernel<<<2048, 256>>>((const float4*)actor_feat,
                                   (const float4*)lane_feat, (float4*)out);
}

// round 10
// speedup vs baseline: 3.9758x; 1.0170x over previous
#include <cuda_runtime.h>
#include <math.h>

// Problem constants
#define Bc   512
#define NAc  128
#define NLc  512
#define Dc   128
#define KAc  16
#define KLc  16
#define NNODES 32   // KA + KL

typedef unsigned long long u64;

// Scratch: computed node rows + selection.
__device__ float g_nodes[(size_t)Bc * NNODES * Dc];   // 8 MB
__device__ int   g_sel[Bc * NNODES];

// ---------------------------------------------------------------------------
// MLP dynamic shared layout (53376 bytes -> 4 blocks/SM)
//   Xs/Hs: float [128][36], transposed [k][row] (stride 36 floats = 144B)
//   Wst:   float [2][2048] double-buffered weight stage (8KB each)
// ---------------------------------------------------------------------------
#define SM_XS    0        // 18432
#define SM_HS    18432    // 18432
#define SM_WST   36864    // 16384
#define SM_SSEL  53248    // 128
#define SM_TOTAL 53376

// ---------------------------------------------------------------------------
// helpers
// ---------------------------------------------------------------------------
__device__ __forceinline__ u64 pk2(float lo, float hi) {
    u64 r;
    asm("mov.b64 %0, {%1, %2};" : "=l"(r) : "f"(lo), "f"(hi));
    return r;
}
__device__ __forceinline__ void fma2(u64& d, u64 a, u64 b) {
    asm("fma.rn.f32x2 %0, %1, %2, %0;" : "+l"(d) : "l"(a), "l"(b));
}
__device__ __forceinline__ void unpk2(u64 v, float& lo, float& hi) {
    asm("mov.b64 {%0, %1}, %2;" : "=f"(lo), "=f"(hi) : "l"(v));
}
__device__ __forceinline__ void cpa16(void* smem_dst, const void* gsrc) {
    unsigned sa = (unsigned)__cvta_generic_to_shared(smem_dst);
    asm volatile("cp.async.cg.shared.global [%0], [%1], 16;"
                 :: "r"(sa), "l"(gsrc));
}
#define CP_COMMIT() asm volatile("cp.async.commit_group;")
#define CP_WAIT0()  asm volatile("cp.async.wait_group 0;")

__device__ __forceinline__ float wsum32(float v) {
    #pragma unroll
    for (int o = 16; o > 0; o >>= 1) v += __shfl_xor_sync(0xffffffffu, v, o);
    return v;
}
__device__ __forceinline__ float gelu_exact(float x) {
    return 0.5f * x * (1.0f + erff(x * 0.70710678118654752440f));
}

// ---------------------------------------------------------------------------
// Kernel 1: selection (proven R2..R9). One block per batch.
// ---------------------------------------------------------------------------
__global__ void __launch_bounds__(128)
select_kernel(const float* __restrict__ lane_centers,
              const float* __restrict__ x_centers,
              const float* __restrict__ spike_rate,
              const void*  __restrict__ actor_valid_raw,
              const void*  __restrict__ lane_valid_raw)
{
    __shared__ float sv[NAc];
    __shared__ float ld[NLc];
    __shared__ int   sel[NNODES];
    __shared__ float ax[KAc], ay[KAc];

    const int tid = threadIdx.x;
    const int b   = blockIdx.x;

    // ---- Phase 0: detect boolean encoding (uint8 / int32 / float32) ----
    int enc;
    {
        const unsigned char* p =
            (const unsigned char*)lane_valid_raw + (size_t)b * 512;
        unsigned char b1 = p[tid * 4 + 1];
        unsigned char b2 = p[tid * 4 + 2];
        unsigned char b3 = p[tid * 4 + 3];
        int any1   = __syncthreads_or((int)b1);
        int anyOff = __syncthreads_or((int)(b1 | b2 | b3));
        enc = anyOff ? (any1 ? 0 : 2) : 1;
    }

    // ---- Phase A: actor top-16 (stable, jax top_k tie rule) ----
    {
        bool av;
        if (enc == 0)      av = ((const unsigned char*)actor_valid_raw)[(size_t)b * NAc + tid] != 0;
        else if (enc == 1) av = ((const int*)actor_valid_raw)[(size_t)b * NAc + tid] != 0;
        else               av = ((const float*)actor_valid_raw)[(size_t)b * NAc + tid] != 0.0f;
        float v = spike_rate[b * NAc + tid];
        sv[tid] = av ? v : -INFINITY;
    }
    __syncthreads();
    {
        float mv = sv[tid];
        int cnt = 0;
        #pragma unroll 8
        for (int j = 0; j < NAc; j++) {
            float o = sv[j];
            cnt += (o > mv) || (o == mv && j < tid);
        }
        if (cnt < KAc) sel[cnt] = tid;
    }
    __syncthreads();
    if (tid < KAc) {
        int a = sel[tid];
        ax[tid] = x_centers[((size_t)b * NAc + a) * 2 + 0];
        ay[tid] = x_centers[((size_t)b * NAc + a) * 2 + 1];
    }
    __syncthreads();

    // ---- Phase B: lane distances + top-16 smallest ----
    #pragma unroll
    for (int q = 0; q < 4; q++) {
        int l = tid + 128 * q;
        bool lv;
        if (enc == 0)      lv = ((const unsigned char*)lane_valid_raw)[(size_t)b * NLc + l] != 0;
        else if (enc == 1) lv = ((const int*)lane_valid_raw)[(size_t)b * NLc + l] != 0;
        else               lv = ((const float*)lane_valid_raw)[(size_t)b * NLc + l] != 0.0f;
        float d = INFINITY;
        if (lv) {
            float lx = lane_centers[((size_t)b * NLc + l) * 2 + 0];
            float ly = lane_centers[((size_t)b * NLc + l) * 2 + 1];
            float m2 = INFINITY;
            #pragma unroll
            for (int a = 0; a < KAc; a++) {
                float dx = __fadd_rn(ax[a], -lx);
                float dy = __fadd_rn(ay[a], -ly);
                float s = __fadd_rn(__fmul_rn(dx, dx), __fmul_rn(dy, dy));
                m2 = fminf(m2, s);
            }
            d = sqrtf(m2);   // sqrt monotone: min(sqrt(s)) == sqrt(min(s))
        }
        ld[l] = d;
    }
    __syncthreads();
    {
        float dl[4];
        int   cnt[4];
        #pragma unroll
        for (int q = 0; q < 4; q++) { dl[q] = ld[tid + 128 * q]; cnt[q] = 0; }
        #pragma unroll 4
        for (int j = 0; j < NLc; j++) {
            float o = ld[j];
            #pragma unroll
            for (int q = 0; q < 4; q++) {
                int l = tid + 128 * q;
                cnt[q] += (o < dl[q]) || (o == dl[q] && j < l);
            }
        }
        #pragma unroll
        for (int q = 0; q < 4; q++)
            if (cnt[q] < KLc) sel[KAc + cnt[q]] = tid + 128 * q;
    }
    __syncthreads();

    if (tid < NNODES) g_sel[b * NNODES + tid] = sel[tid];
}

// ---------------------------------------------------------------------------
// 32x128 @ 128x128 GEMM, 128 threads, cp.async double-buffered W.
// A: float [128][36] transposed [k][row]. Warp rg (tid>>5): rows 8rg..8rg+7
// (two broadcast LDS.128 -> four row-pair u64s). Lane cg (tid&31): cols
// 4cg..4cg+3 (one conflict-free LDS.128, 4 pk2 dups).
// Per kk: 3 LDS + 4 pk2 + 16 fma2  (0.375 wf/fma2 vs 0.625 in R9).
// ---------------------------------------------------------------------------
__device__ __forceinline__ void gemm_rc8(
    const float* A, const float* __restrict__ Wg,
    float* Wst, int tid, int rg, int cg, u64 (&acc)[4][4])
{
    #pragma unroll
    for (int rp = 0; rp < 4; rp++)
        #pragma unroll
        for (int c = 0; c < 4; c++) acc[rp][c] = 0ull;

    // prologue: stage 0 (16x128 fp32 = 8KB), 4x16B per thread
    #pragma unroll
    for (int i = 0; i < 4; i++)
        cpa16(Wst + (tid + 128 * i) * 4, Wg + (tid + 128 * i) * 4);
    CP_COMMIT();

    #pragma unroll 1
    for (int s = 0; s < 8; s++) {
        CP_WAIT0();          // stage-s copies landed
        __syncthreads();     // visible to all; prior stage reads complete
        if (s < 7) {
            float* dst = Wst + ((s + 1) & 1) * 2048;
            const float* src = Wg + (s + 1) * 2048;
            #pragma unroll
            for (int i = 0; i < 4; i++)
                cpa16(dst + (tid + 128 * i) * 4, src + (tid + 128 * i) * 4);
            CP_COMMIT();
        }
        const float* Ws = Wst + (s & 1) * 2048;
        const float* Ab = A + s * 16 * 36 + 8 * rg;
        #pragma unroll
        for (int kk = 0; kk < 16; kk++) {
            float4 w = *(const float4*)(Ws + kk * 128 + 4 * cg);
            u64 bx = pk2(w.x, w.x);
            u64 by = pk2(w.y, w.y);
            u64 bz = pk2(w.z, w.z);
            u64 bw = pk2(w.w, w.w);
            ulonglong2 a01 = *(const ulonglong2*)(Ab + kk * 36);      // rows 8rg..+3
            ulonglong2 a23 = *(const ulonglong2*)(Ab + kk * 36 + 4);  // rows 8rg+4..+7
            fma2(acc[0][0], a01.x, bx); fma2(acc[0][1], a01.x, by);
            fma2(acc[0][2], a01.x, bz); fma2(acc[0][3], a01.x, bw);
            fma2(acc[1][0], a01.y, bx); fma2(acc[1][1], a01.y, by);
            fma2(acc[1][2], a01.y, bz); fma2(acc[1][3], a01.y, bw);
            fma2(acc[2][0], a23.x, bx); fma2(acc[2][1], a23.x, by);
            fma2(acc[2][2], a23.x, bz); fma2(acc[2][3], a23.x, bw);
            fma2(acc[3][0], a23.y, bx); fma2(acc[3][1], a23.y, by);
            fma2(acc[3][2], a23.y, bz); fma2(acc[3][3], a23.y, bw);
        }
    }
}

// ---------------------------------------------------------------------------
// Kernel 2: MLP. One batch per block, 128 threads, 4 blocks/SM.
// ---------------------------------------------------------------------------
__global__ void __launch_bounds__(128, 4)
mlp_kernel(const float* __restrict__ actor_feat,
           const float* __restrict__ lane_feat,
           const float* __restrict__ W0a, const float* __restrict__ b0a,
           const float* __restrict__ W0b, const float* __restrict__ b0b,
           const float* __restrict__ W1a, const float* __restrict__ b1a,
           const float* __restrict__ W1b, const float* __restrict__ b1b,
           const float* __restrict__ gmm, const float* __restrict__ bta)
{
    extern __shared__ unsigned char smem_raw[];
    float* Xs  = (float*)(smem_raw + SM_XS);    // [k][row], stride 36
    float* Hs  = (float*)(smem_raw + SM_HS);
    float* Wst = (float*)(smem_raw + SM_WST);
    int*  ssel = (int*)(smem_raw + SM_SSEL);

    const int tid = threadIdx.x;
    const int b   = blockIdx.x;
    const int rg  = tid >> 5;    // warp -> rows 8rg..8rg+7
    const int cg  = tid & 31;    // lane -> cols 4cg..4cg+3

    if (tid < NNODES) ssel[tid] = g_sel[b * NNODES + tid];
    __syncthreads();

    // ---- gather: thread = feature column; 32 node rows ----
    #pragma unroll 4
    for (int rw = 0; rw < NNODES; rw++) {
        int idx = ssel[rw];
        const float* src = (rw < KAc)
            ? (actor_feat + ((size_t)b * NAc + idx) * Dc)
            : (lane_feat  + ((size_t)b * NLc + idx) * Dc);
        Xs[tid * 36 + rw] = src[tid];
    }
    // visibility to GEMM1 reads: behind gemm_rc8's stage-0 sync

    u64 acc[4][4];

    #pragma unroll 1
    for (int layer = 0; layer < 2; layer++) {
        const float* Wa  = layer ? W1a : W0a;
        const float* ba  = layer ? b1a : b0a;
        const float* Wb2 = layer ? W1b : W0b;
        const float* bb2 = layer ? b1b : b0b;

        // ---- GEMM1: H = gelu(X @ Wa + ba) -> Hs ----
        gemm_rc8(Xs, Wa, Wst, tid, rg, cg, acc);
        {
            float4 bq = *(const float4*)(ba + 4 * cg);
            float bar[4] = {bq.x, bq.y, bq.z, bq.w};
            #pragma unroll
            for (int rp = 0; rp < 4; rp++) {
                int r0 = 8 * rg + 2 * rp;
                #pragma unroll
                for (int c = 0; c < 4; c++) {
                    float lo, hi; unpk2(acc[rp][c], lo, hi);
                    lo = gelu_exact(lo + bar[c]);
                    hi = gelu_exact(hi + bar[c]);
                    *(float2*)(Hs + (4 * cg + c) * 36 + r0) = make_float2(lo, hi);
                }
            }
        }
        // Hs writes vs GEMM2 reads: behind gemm_rc8's stage-0 sync

        // ---- GEMM2: Y = H @ Wb + bb; Z = LN(X + Y) ----
        gemm_rc8(Hs, Wb2, Wst, tid, rg, cg, acc);
        {
            float4 bq = *(const float4*)(bb2 + 4 * cg);
            float bbr[4] = {bq.x, bq.y, bq.z, bq.w};
            float4 gq = *(const float4*)(gmm + 4 * cg);
            float4 pq = *(const float4*)(bta + 4 * cg);
            float gar[4] = {gq.x, gq.y, gq.z, gq.w};
            float per[4] = {pq.x, pq.y, pq.z, pq.w};

            #pragma unroll
            for (int rp = 0; rp < 4; rp++) {
                int r0 = 8 * rg + 2 * rp;
                float l0[4], l1[4];
                #pragma unroll
                for (int c = 0; c < 4; c++) {
                    float lo, hi; unpk2(acc[rp][c], lo, hi);
                    float2 xv = *(const float2*)(Xs + (4 * cg + c) * 36 + r0);
                    l0[c] = lo + bbr[c] + xv.x;
                    l1[c] = hi + bbr[c] + xv.y;
                }
                float m0 = wsum32(l0[0] + l0[1] + l0[2] + l0[3]) * 0.0078125f;
                float m1 = wsum32(l1[0] + l1[1] + l1[2] + l1[3]) * 0.0078125f;
                float q0 = 0.f, q1 = 0.f;
                #pragma unroll
                for (int c = 0; c < 4; c++) {
                    float d0 = l0[c] - m0; q0 += d0 * d0;
                    float d1 = l1[c] - m1; q1 += d1 * d1;
                }
                float i0 = rsqrtf(wsum32(q0) * 0.0078125f + 1e-5f);
                float i1 = rsqrtf(wsum32(q1) * 0.0078125f + 1e-5f);

                if (layer == 0) {
                    #pragma unroll
                    for (int c = 0; c < 4; c++) {
                        float z0 = (l0[c] - m0) * i0 * gar[c] + per[c];
                        float z1 = (l1[c] - m1) * i1 * gar[c] + per[c];
                        *(float2*)(Xs + (4 * cg + c) * 36 + r0) = make_float2(z0, z1);
                    }
                } else {
                    float4 o0, o1;
                    o0.x = (l0[0] - m0) * i0 * gar[0] + per[0];
                    o0.y = (l0[1] - m0) * i0 * gar[1] + per[1];
                    o0.z = (l0[2] - m0) * i0 * gar[2] + per[2];
                    o0.w = (l0[3] - m0) * i0 * gar[3] + per[3];
                    o1.x = (l1[0] - m1) * i1 * gar[0] + per[0];
                    o1.y = (l1[1] - m1) * i1 * gar[1] + per[1];
                    o1.z = (l1[2] - m1) * i1 * gar[2] + per[2];
                    o1.w = (l1[3] - m1) * i1 * gar[3] + per[3];
                    float* d0 = g_nodes + ((size_t)b * NNODES + r0) * Dc + 4 * cg;
                    *(float4*)d0        = o0;
                    *(float4*)(d0 + Dc) = o1;
                }
            }
        }
    }
}

// ---------------------------------------------------------------------------
// Scatter kernel: warp per row, float4 lanes (measured 7us).
// ---------------------------------------------------------------------------
__global__ void __launch_bounds__(256)
scatter_kernel(float* __restrict__ out)
{
    __shared__ int ssel[NNODES];
    const int tid = threadIdx.x;
    const int b   = blockIdx.x;
    if (tid < NNODES) ssel[tid] = g_sel[b * NNODES + tid];
    __syncthreads();
    const int w = tid >> 5, lane = tid & 31;
    const size_t lane_base = (size_t)Bc * NAc * Dc;
    #pragma unroll
    for (int it = 0; it < 4; it++) {
        int rr = it * 8 + w;
        int idx = ssel[rr];
        size_t base = (rr < KAc)
            ? ((size_t)b * NAc + idx) * Dc
            : lane_base + ((size_t)b * NLc + idx) * Dc;
        ((float4*)(out + base))[lane] =
            ((const float4*)(g_nodes + ((size_t)b * NNODES + rr) * Dc))[lane];
    }
}

__global__ void nop_kernel() {}

// ---------------------------------------------------------------------------
// kernel_launch: select -> nop,nop -> mlp -> CE memcpys -> scatter.
// Kernel order matches R9 (mlp is 4th kernel) so ncu captures mlp again.
// ---------------------------------------------------------------------------
extern "C" void kernel_launch(void* const* d_in, const int* in_sizes, int n_in,
                              void* d_out, int out_size)
{
    const float* actor_feat   = (const float*)d_in[0];
    const float* lane_feat    = (const float*)d_in[1];
    const float* lane_centers = (const float*)d_in[2];
    const float* x_centers    = (const float*)d_in[3];
    const float* spike_rate   = (const float*)d_in[4];
    const void*  actor_valid  = d_in[5];
    const void*  lane_valid   = d_in[6];
    const float* W0a = (const float*)d_in[7];
    const float* b0a = (const float*)d_in[8];
    const float* W0b = (const float*)d_in[9];
    const float* b0b = (const float*)d_in[10];
    const float* W1a = (const float*)d_in[11];
    const float* b1a = (const float*)d_in[12];
    const float* W1b = (const float*)d_in[13];
    const float* b1b = (const float*)d_in[14];
    const float* gmm = (const float*)d_in[15];
    const float* bta = (const float*)d_in[16];
    float* out = (float*)d_out;

    const size_t actor_elems = (size_t)Bc * NAc * Dc;
    const size_t lane_elems  = (size_t)Bc * NLc * Dc;

    cudaFuncSetAttribute(mlp_kernel,
                         cudaFuncAttributeMaxDynamicSharedMemorySize, SM_TOTAL);

    select_kernel<<<Bc, 128>>>(lane_centers, x_centers, spike_rate,
                               actor_valid, lane_valid);
    nop_kernel<<<1, 32>>>();
    nop_kernel<<<1, 32>>>();
    mlp_kernel<<<Bc, 128, SM_TOTAL>>>(actor_feat, lane_feat,
                                      W0a, b0a, W0b, b0b,
                                      W1a, b1a, W1b, b1b,
                                      gmm, bta);

    // Bulk pool copy into out (copy engine), then overwrite selected rows.
    cudaMemcpyAsync(out, actor_feat, actor_elems * sizeof(float),
                    cudaMemcpyDeviceToDevice, 0);
    cudaMemcpyAsync(out + actor_elems, lane_feat, lane_elems * sizeof(float),
                    cudaMemcpyDeviceToDevice, 0);

    scatter_kernel<<<Bc, 256>>>(out);
}